// round 12
// baseline (speedup 1.0000x reference)
#include <cuda_runtime.h>
#include <cuda_fp16.h>

// SpectrumEncoding: out[b,d] = sum_n pe[ceil(loc[b,n]*10), d] * inten[b,n]
// B=1024, N=500, D=512.
//
// R11 falsified latency-binding: regs 32->78, occ 79->33%, dur identical.
// Gather is l1tex-wavefront-rate bound; LDG.128 pays the within-LDG replay
// rate (~2.07 cyc/wf). R12: LDG.32 — warp = one 128B line = one wavefront at
// the cross-LDG 1.0 rate. 256 thr/CTA (thread owns one half2 of the row),
// grid 1024 (exclusive rows: no atomics/zeroing), peak (idx,w2) broadcast by
// 2 SHFLs from 25-peak register chunks (LDS off the hot path).

#define N_PEAKS    500
#define D_MODEL    512
#define RESO       10.0f
#define TABLE_ROWS 30001
#define ROW_U      (D_MODEL / 2)   // 256 uints (half2) per fp16 row

// fp16 copy of pe, rebuilt each call (30.7 MB).
__device__ unsigned g_peh[TABLE_ROWS * ROW_U];

// ---------------------------------------------------------------------------
// Pass 1: f32 -> f16 convert (8-deep unroll, MLP=8). ~HBM floor (~10.5us).
// ---------------------------------------------------------------------------
__global__ void convert_pe_kernel(const float4* __restrict__ pe4)
{
    uint2* __restrict__ dst = reinterpret_cast<uint2*>(g_peh);
    const int total  = TABLE_ROWS * (D_MODEL / 4);   // 3,840,128 uint2
    const int stride = gridDim.x * blockDim.x;       // 524,288
    const int i0     = blockIdx.x * blockDim.x + threadIdx.x;

    #pragma unroll 8
    for (int j = 0; j < 8; ++j) {
        const int k = i0 + j * stride;
        if (k < total) {
            float4 v = pe4[k];
            __half2 h0 = __floats2half2_rn(v.x, v.y);
            __half2 h1 = __floats2half2_rn(v.z, v.w);
            uint2 p;
            p.x = *reinterpret_cast<unsigned*>(&h0);
            p.y = *reinterpret_cast<unsigned*>(&h1);
            dst[k] = p;
        }
    }
}

// ---------------------------------------------------------------------------
// Pass 2: gather + weighted reduce. One CTA per batch row. 256 threads,
// thread t owns uint t (half2) of each gathered row. 500 peaks in 20 chunks
// of 25: one coalesced LDS.64 per chunk (lanes 0..24 hold peaks), then 25
// iters of 2xSHFL + LDG.32 + HFMA2, fp16 chains of 5 flushed to f32.
// ---------------------------------------------------------------------------
__global__ __launch_bounds__(256)
void SpectrumEncoding_kernel(const float*  __restrict__ loc,
                             const float*  __restrict__ inten,
                             float2*       __restrict__ out2)
{
    __shared__ float2 s_iw[N_PEAKS];  // .x = (idx*ROW_U) bits, .y = half2(w,w) bits

    const int b    = blockIdx.x;
    const int t    = threadIdx.x;
    const int lane = t & 31;

    const float* lrow = loc   + (long long)b * N_PEAKS;
    const float* irow = inten + (long long)b * N_PEAKS;

    for (int n = t; n < N_PEAKS; n += 256) {
        int idx = (int)ceilf(lrow[n] * RESO);
        __half2 w2 = __half2half2(__float2half(irow[n]));
        s_iw[n] = make_float2(__int_as_float(idx * ROW_U),
                              __uint_as_float(*reinterpret_cast<unsigned*>(&w2)));
    }
    __syncthreads();

    float2 acc = make_float2(0.f, 0.f);

    for (int chunk = 0; chunk < 20; ++chunk) {
        // Lanes 0..24 hold this chunk's 25 (idx, w2) pairs in registers.
        const int ln = lane < 25 ? lane : 24;
        const float2 my = s_iw[chunk * 25 + ln];
        const int      my_idx = __float_as_int(my.x);
        const unsigned my_w   = __float_as_uint(my.y);

        #pragma unroll
        for (int jb = 0; jb < 5; ++jb) {
            __half2 h = __half2half2(__ushort_as_half(0));
            #pragma unroll
            for (int j5 = 0; j5 < 5; ++j5) {
                const int j = jb * 5 + j5;
                const int      idxp = __shfl_sync(0xffffffffu, my_idx, j);
                const unsigned wb   = __shfl_sync(0xffffffffu, my_w,   j);
                const __half2  w2   = *reinterpret_cast<const __half2*>(&wb);
                const unsigned v    = __ldg(&g_peh[idxp + t]);
                h = __hfma2(*reinterpret_cast<const __half2*>(&v), w2, h);
            }
            const float2 f = __half22float2(h);
            acc.x += f.x;
            acc.y += f.y;
        }
    }

    out2[(long long)b * ROW_U + t] = acc;   // exclusive, coalesced STG.64
}

extern "C" void kernel_launch(void* const* d_in, const int* in_sizes, int n_in,
                              void* d_out, int out_size)
{
    const float*  loc   = (const float*)d_in[0];   // [B, 500]
    const float*  inten = (const float*)d_in[1];   // [B, 500]
    const float4* pe4   = (const float4*)d_in[2];  // [30001, 512] f32
    float2*       out2  = (float2*)d_out;          // [B, 512] f32

    const int B = in_sizes[0] / N_PEAKS;           // 1024

    convert_pe_kernel<<<2048, 256>>>(pe4);
    SpectrumEncoding_kernel<<<B, 256>>>(loc, inten, out2);
}

// round 13
// speedup vs baseline: 1.3583x; 1.3583x over previous
#include <cuda_runtime.h>
#include <cuda_fp16.h>

// SpectrumEncoding: out[b,d] = sum_n pe[ceil(loc[b,n]*10), d] * inten[b,n]
// B=1024, N=500, D=512.
//
// R12: LDG.32 hit the 4cyc LDG->LDG dispatch floor (58us) -> reverted.
// Standing mystery: fp16 LDG.128 gather caps at ~12.8TB/s (L2 56%) while the
// f32 gather reached ~17TB/s (L2 74%), invariant to MLP/occ/schedule.
// Hypothesis: 1KB row fetches only vary L2 slice-hash bit {8} (2 slice
// groups/fetch) vs 2KB fetches varying {8,10} (4 groups) -> LTS queueing.
// R13: plane-split layout — fp16 row stored as two 512B halves 15.4MB apart,
// restoring ~4-way slice spread per row fetch. Gather loop is otherwise
// identical to the proven R9/R10 structure.

#define N_PEAKS    500
#define HALF_PEAKS 250
#define D_MODEL    512
#define RESO       10.0f
#define TABLE_ROWS 30001
#define PLANE_U4   (TABLE_ROWS * 32)   // 512B half-row = 32 uint4
#define PLANE_U2   (TABLE_ROWS * 64)   // same in uint2 units

// fp16 table, plane-split: plane p (0/1) holds half p of every row.
__device__ uint4 g_peh[2 * PLANE_U4];  // 30.7 MB

// ---------------------------------------------------------------------------
// Pass 1: f32 -> f16 convert into the plane-split layout (8-deep unroll,
// MLP=8) + zero d_out (grid*block == 524288 == out element count).
// ---------------------------------------------------------------------------
__global__ void convert_pe_kernel(const float4* __restrict__ pe4,
                                  float*        __restrict__ out)
{
    uint2* __restrict__ dst = reinterpret_cast<uint2*>(g_peh);
    const int total  = TABLE_ROWS * 128;             // u2 granules (8B each)
    const int stride = gridDim.x * blockDim.x;       // 524,288
    const int i0     = blockIdx.x * blockDim.x + threadIdx.x;

    out[i0] = 0.0f;

    #pragma unroll 8
    for (int j = 0; j < 8; ++j) {
        const int k = i0 + j * stride;
        if (k < total) {
            const int row = k >> 7;                  // source row
            const int c   = k & 127;                 // u2 granule within row
            const int p   = c >> 6;                  // plane (half) 0/1
            const int q   = c & 63;                  // u2 within half
            float4 v = pe4[k];
            __half2 h0 = __floats2half2_rn(v.x, v.y);
            __half2 h1 = __floats2half2_rn(v.z, v.w);
            uint2 pk;
            pk.x = *reinterpret_cast<unsigned*>(&h0);
            pk.y = *reinterpret_cast<unsigned*>(&h1);
            dst[p * PLANE_U2 + (row << 6) + q] = pk;
        }
    }
}

// ---------------------------------------------------------------------------
// Pass 2: gather + weighted reduce.
// CTA = (batch row, peak half): 250 peaks. 128 threads = 2 groups of 64;
// group g handles peak 2*it+g. Thread t64: plane = t64>>5, slot = t64&31 —
// a per-thread constant base; per peak one LDG.128 at base + idx*32.
// fp16 HFMA2 chains of 5 flushed to f32. Epilogue: smem combine of the 2
// groups, then 8 atomicAdds (2 contenders per address).
// ---------------------------------------------------------------------------
__global__ __launch_bounds__(128)
void SpectrumEncoding_kernel(const float*  __restrict__ loc,
                             const float*  __restrict__ inten,
                             float*        __restrict__ out)
{
    __shared__ float2 s_iw[HALF_PEAKS];  // .x = (idx*32) bits, .y = half2(w,w) bits
    __shared__ float4 s_red[128];        // group-1 accumulators (2 KB)

    const int cta  = blockIdx.x;         // 0..2047
    const int b    = cta >> 1;
    const int nbeg = (cta & 1) * HALF_PEAKS;
    const int t    = threadIdx.x;
    const int g    = t >> 6;             // thread-group 0/1 (2 warps each)
    const int t64  = t & 63;

    // Per-thread constant: plane base + slot within the 512B half.
    const int tbase = (t64 >> 5) * PLANE_U4 + (t64 & 31);
    // Output column this thread's 16B covers: 8 contiguous halves.
    const int col0  = ((t64 >> 5) << 8) + ((t64 & 31) << 3);

    const float* lrow = loc   + (long long)b * N_PEAKS + nbeg;
    const float* irow = inten + (long long)b * N_PEAKS + nbeg;

    for (int n = t; n < HALF_PEAKS; n += 128) {
        int idx = (int)ceilf(lrow[n] * RESO);
        __half2 w2 = __half2half2(__float2half(irow[n]));
        s_iw[n] = make_float2(__int_as_float(idx * 32),
                              __uint_as_float(*reinterpret_cast<unsigned*>(&w2)));
    }
    __syncthreads();

    float4 a0 = make_float4(0.f, 0.f, 0.f, 0.f);
    float4 a1 = make_float4(0.f, 0.f, 0.f, 0.f);

    for (int blk = 0; blk < 25; ++blk) {
        __half2 h0 = __half2half2(__ushort_as_half(0));
        __half2 h1 = h0, h2 = h0, h3 = h0;

        #pragma unroll
        for (int j = 0; j < 5; ++j) {
            const int n = (blk * 5 + j) * 2 + g;
            const float2 iw = s_iw[n];                 // warp-uniform broadcast
            const unsigned wb = __float_as_uint(iw.y);
            const __half2  w2 = *reinterpret_cast<const __half2*>(&wb);
            const uint4    v  = __ldg(&g_peh[tbase + __float_as_int(iw.x)]);
            h0 = __hfma2(*reinterpret_cast<const __half2*>(&v.x), w2, h0);
            h1 = __hfma2(*reinterpret_cast<const __half2*>(&v.y), w2, h1);
            h2 = __hfma2(*reinterpret_cast<const __half2*>(&v.z), w2, h2);
            h3 = __hfma2(*reinterpret_cast<const __half2*>(&v.w), w2, h3);
        }

        const float2 f0 = __half22float2(h0);
        const float2 f1 = __half22float2(h1);
        const float2 f2 = __half22float2(h2);
        const float2 f3 = __half22float2(h3);
        a0.x += f0.x; a0.y += f0.y; a0.z += f1.x; a0.w += f1.y;
        a1.x += f2.x; a1.y += f2.y; a1.z += f3.x; a1.w += f3.y;
    }

    // Combine the two peak-groups, then atomically add into out
    // (exactly 2 contenders per address: the two peak-half CTAs).
    if (g == 1) {
        s_red[t64]      = a0;
        s_red[64 + t64] = a1;
    }
    __syncthreads();
    if (g == 0) {
        const float4 b0 = s_red[t64];
        const float4 b1 = s_red[64 + t64];
        a0.x += b0.x; a0.y += b0.y; a0.z += b0.z; a0.w += b0.w;
        a1.x += b1.x; a1.y += b1.y; a1.z += b1.z; a1.w += b1.w;
        float* orow = out + (long long)b * D_MODEL + col0;
        atomicAdd(orow + 0, a0.x);
        atomicAdd(orow + 1, a0.y);
        atomicAdd(orow + 2, a0.z);
        atomicAdd(orow + 3, a0.w);
        atomicAdd(orow + 4, a1.x);
        atomicAdd(orow + 5, a1.y);
        atomicAdd(orow + 6, a1.z);
        atomicAdd(orow + 7, a1.w);
    }
}

extern "C" void kernel_launch(void* const* d_in, const int* in_sizes, int n_in,
                              void* d_out, int out_size)
{
    const float*  loc   = (const float*)d_in[0];   // [B, 500]
    const float*  inten = (const float*)d_in[1];   // [B, 500]
    const float4* pe4   = (const float4*)d_in[2];  // [30001, 512] f32
    float*        out   = (float*)d_out;           // [B, 512] f32

    const int B = in_sizes[0] / N_PEAKS;           // 1024

    convert_pe_kernel<<<2048, 256>>>(pe4, out);    // 524288 threads == out elems
    SpectrumEncoding_kernel<<<B * 2, 128>>>(loc, inten, out);
}

// round 14
// speedup vs baseline: 1.3592x; 1.0006x over previous
#include <cuda_runtime.h>
#include <cuda_fp16.h>

// SpectrumEncoding: out[b,d] = sum_n pe[ceil(loc[b,n]*10), d] * inten[b,n]
// B=1024, N=500, D=512.
//
// R13 falsified L2-slice-diversity (plane-split identical). fp16 gather sits
// 1.25x above the l1tex wavefront floor; f32 sat at ~1.0x. Last untested
// path knob: L1 allocation. Gathered lines are use-once (hit prob ~0.7% on a
// 30MB random table) -> L1 allocate+evict per wavefront is pure overhead.
// R14: single-variable experiment — ld.global.cg (L1-bypass) row loads on
// the otherwise-frozen R9/R13 kernel (linear layout restored).

#define N_PEAKS    500
#define HALF_PEAKS 250
#define D_MODEL    512
#define RESO       10.0f
#define TABLE_ROWS 30001
#define ROW_U4     (D_MODEL / 8) // 64 uint4 (8 halves) per fp16 row

// fp16 copy of pe, rebuilt each call (30.7 MB).
__device__ uint4 g_peh[TABLE_ROWS * ROW_U4];

__device__ __forceinline__ uint4 ldg_cg_v4(const uint4* p)
{
    uint4 v;
    asm volatile("ld.global.cg.v4.u32 {%0,%1,%2,%3}, [%4];"
                 : "=r"(v.x), "=r"(v.y), "=r"(v.z), "=r"(v.w)
                 : "l"(p));
    return v;
}

// ---------------------------------------------------------------------------
// Pass 1: f32 -> f16 convert (8-deep unroll, MLP=8) + zero d_out.
// Grid is exactly 2048*256 = 524288 threads = out element count.
// ---------------------------------------------------------------------------
__global__ void convert_pe_kernel(const float4* __restrict__ pe4,
                                  float*        __restrict__ out)
{
    uint2* __restrict__ dst = reinterpret_cast<uint2*>(g_peh);
    const int total  = TABLE_ROWS * (D_MODEL / 4);   // 3,840,128 uint2
    const int stride = gridDim.x * blockDim.x;       // 524,288
    const int i0     = blockIdx.x * blockDim.x + threadIdx.x;

    out[i0] = 0.0f;

    #pragma unroll 8
    for (int j = 0; j < 8; ++j) {
        const int k = i0 + j * stride;
        if (k < total) {
            float4 v = pe4[k];
            __half2 h0 = __floats2half2_rn(v.x, v.y);
            __half2 h1 = __floats2half2_rn(v.z, v.w);
            uint2 p;
            p.x = *reinterpret_cast<unsigned*>(&h0);
            p.y = *reinterpret_cast<unsigned*>(&h1);
            dst[k] = p;
        }
    }
}

// ---------------------------------------------------------------------------
// Pass 2: gather + weighted reduce.
// CTA = (batch row, peak half): 250 peaks. 128 threads = 2 groups of 64;
// group g handles peak 2*it+g. Per peak: LDS.64 (iw, warp-uniform) +
// ld.global.cg.v4 row load + 4 HFMA2; fp16 chains of 5 flushed to f32.
// Epilogue: smem combine of the 2 groups + 8 atomicAdds (2 contenders/addr).
// ---------------------------------------------------------------------------
__global__ __launch_bounds__(128)
void SpectrumEncoding_kernel(const float*  __restrict__ loc,
                             const float*  __restrict__ inten,
                             float*        __restrict__ out)
{
    __shared__ float2 s_iw[HALF_PEAKS];  // .x = (idx*ROW_U4) bits, .y = half2(w,w) bits
    __shared__ float4 s_red[128];        // group-1 accumulators (2 KB)

    const int cta  = blockIdx.x;         // 0..2047
    const int b    = cta >> 1;
    const int nbeg = (cta & 1) * HALF_PEAKS;
    const int t    = threadIdx.x;
    const int g    = t >> 6;             // thread-group 0/1 (2 warps each)
    const int t64  = t & 63;

    const float* lrow = loc   + (long long)b * N_PEAKS + nbeg;
    const float* irow = inten + (long long)b * N_PEAKS + nbeg;

    for (int n = t; n < HALF_PEAKS; n += 128) {
        int idx = (int)ceilf(lrow[n] * RESO);
        __half2 w2 = __half2half2(__float2half(irow[n]));
        s_iw[n] = make_float2(__int_as_float(idx * ROW_U4),
                              __uint_as_float(*reinterpret_cast<unsigned*>(&w2)));
    }
    __syncthreads();

    float4 a0 = make_float4(0.f, 0.f, 0.f, 0.f);
    float4 a1 = make_float4(0.f, 0.f, 0.f, 0.f);

    for (int blk = 0; blk < 25; ++blk) {
        __half2 h0 = __half2half2(__ushort_as_half(0));
        __half2 h1 = h0, h2 = h0, h3 = h0;

        #pragma unroll
        for (int j = 0; j < 5; ++j) {
            const int n = (blk * 5 + j) * 2 + g;
            const float2 iw = s_iw[n];                 // warp-uniform broadcast
            const unsigned wb = __float_as_uint(iw.y);
            const __half2  w2 = *reinterpret_cast<const __half2*>(&wb);
            const uint4    v  = ldg_cg_v4(&g_peh[__float_as_int(iw.x) + t64]);
            h0 = __hfma2(*reinterpret_cast<const __half2*>(&v.x), w2, h0);
            h1 = __hfma2(*reinterpret_cast<const __half2*>(&v.y), w2, h1);
            h2 = __hfma2(*reinterpret_cast<const __half2*>(&v.z), w2, h2);
            h3 = __hfma2(*reinterpret_cast<const __half2*>(&v.w), w2, h3);
        }

        const float2 f0 = __half22float2(h0);
        const float2 f1 = __half22float2(h1);
        const float2 f2 = __half22float2(h2);
        const float2 f3 = __half22float2(h3);
        a0.x += f0.x; a0.y += f0.y; a0.z += f1.x; a0.w += f1.y;
        a1.x += f2.x; a1.y += f2.y; a1.z += f3.x; a1.w += f3.y;
    }

    // Combine the two peak-groups, then atomically add into out
    // (exactly 2 contenders per address: the two peak-half CTAs).
    if (g == 1) {
        s_red[t64]      = a0;
        s_red[64 + t64] = a1;
    }
    __syncthreads();
    if (g == 0) {
        const float4 b0 = s_red[t64];
        const float4 b1 = s_red[64 + t64];
        a0.x += b0.x; a0.y += b0.y; a0.z += b0.z; a0.w += b0.w;
        a1.x += b1.x; a1.y += b1.y; a1.z += b1.z; a1.w += b1.w;
        float* orow = out + (long long)b * D_MODEL + 8 * t64;
        atomicAdd(orow + 0, a0.x);
        atomicAdd(orow + 1, a0.y);
        atomicAdd(orow + 2, a0.z);
        atomicAdd(orow + 3, a0.w);
        atomicAdd(orow + 4, a1.x);
        atomicAdd(orow + 5, a1.y);
        atomicAdd(orow + 6, a1.z);
        atomicAdd(orow + 7, a1.w);
    }
}

extern "C" void kernel_launch(void* const* d_in, const int* in_sizes, int n_in,
                              void* d_out, int out_size)
{
    const float*  loc   = (const float*)d_in[0];   // [B, 500]
    const float*  inten = (const float*)d_in[1];   // [B, 500]
    const float4* pe4   = (const float4*)d_in[2];  // [30001, 512] f32
    float*        out   = (float*)d_out;           // [B, 512] f32

    const int B = in_sizes[0] / N_PEAKS;           // 1024

    convert_pe_kernel<<<2048, 256>>>(pe4, out);    // 524288 threads == out elems
    SpectrumEncoding_kernel<<<B * 2, 128>>>(loc, inten, out);
}

// round 15
// speedup vs baseline: 1.3694x; 1.0076x over previous
#include <cuda_runtime.h>
#include <cuda_fp16.h>

// SpectrumEncoding: out[b,d] = sum_n pe[ceil(loc[b,n]*10), d] * inten[b,n]
// B=1024, N=500, D=512.
//
// Little's-law fit across R1..R14: gather throughput tracks in-flight
// requests/SM, which sat at ~50 in EVERY fp16 config (high-occ/low-MLP or
// low-occ/high-MLP). R1 f32 reached ~75-80 with 54 regs at 42% occ. The
// untested cell: MLP=5 AND ~30 warps -> needs regs<=64 at 8 CTAs/SM.
// R15 = R11 staged-5 body + __launch_bounds__(128, 8) to force it.

#define N_PEAKS    500
#define HALF_PEAKS 250
#define D_MODEL    512
#define RESO       10.0f
#define TABLE_ROWS 30001
#define ROW_U4     (D_MODEL / 8) // 64 uint4 (8 halves) per fp16 row

// fp16 copy of pe, rebuilt each call (30.7 MB).
__device__ uint4 g_peh[TABLE_ROWS * ROW_U4];

// ---------------------------------------------------------------------------
// Pass 1: f32 -> f16 convert (8-deep unroll, MLP=8) + zero d_out.
// Grid is exactly 2048*256 = 524288 threads = out element count.
// ---------------------------------------------------------------------------
__global__ void convert_pe_kernel(const float4* __restrict__ pe4,
                                  float*        __restrict__ out)
{
    uint2* __restrict__ dst = reinterpret_cast<uint2*>(g_peh);
    const int total  = TABLE_ROWS * (D_MODEL / 4);   // 3,840,128 uint2
    const int stride = gridDim.x * blockDim.x;       // 524,288
    const int i0     = blockIdx.x * blockDim.x + threadIdx.x;

    out[i0] = 0.0f;

    #pragma unroll 8
    for (int j = 0; j < 8; ++j) {
        const int k = i0 + j * stride;
        if (k < total) {
            float4 v = pe4[k];
            __half2 h0 = __floats2half2_rn(v.x, v.y);
            __half2 h1 = __floats2half2_rn(v.z, v.w);
            uint2 p;
            p.x = *reinterpret_cast<unsigned*>(&h0);
            p.y = *reinterpret_cast<unsigned*>(&h1);
            dst[k] = p;
        }
    }
}

// ---------------------------------------------------------------------------
// Pass 2: gather + weighted reduce.
// CTA = (batch row, peak half): 250 peaks. 128 threads = 2 groups of 64;
// group g handles peak 2*it+g. Per 5-block: 5 LDS, 5 independent LDG.128
// held live (MLP=5), fp16 HFMA2 chains of 5, flush to f32. launch_bounds
// (128, 8) caps regs at 64 so MLP=5 coexists with ~32 warps/SM.
// Epilogue: smem combine of the 2 groups + 8 atomicAdds (2 contenders/addr).
// ---------------------------------------------------------------------------
__global__ __launch_bounds__(128, 8)
void SpectrumEncoding_kernel(const float*  __restrict__ loc,
                             const float*  __restrict__ inten,
                             float*        __restrict__ out)
{
    __shared__ float2 s_iw[HALF_PEAKS];  // .x = (idx*ROW_U4) bits, .y = half2(w,w) bits
    __shared__ float4 s_red[128];        // group-1 accumulators (2 KB)

    const int cta  = blockIdx.x;         // 0..2047
    const int b    = cta >> 1;
    const int nbeg = (cta & 1) * HALF_PEAKS;
    const int t    = threadIdx.x;
    const int g    = t >> 6;             // thread-group 0/1 (2 warps each)
    const int t64  = t & 63;

    const float* lrow = loc   + (long long)b * N_PEAKS + nbeg;
    const float* irow = inten + (long long)b * N_PEAKS + nbeg;

    for (int n = t; n < HALF_PEAKS; n += 128) {
        int idx = (int)ceilf(lrow[n] * RESO);
        __half2 w2 = __half2half2(__float2half(irow[n]));
        s_iw[n] = make_float2(__int_as_float(idx * ROW_U4),
                              __uint_as_float(*reinterpret_cast<unsigned*>(&w2)));
    }
    __syncthreads();

    float4 a0 = make_float4(0.f, 0.f, 0.f, 0.f);
    float4 a1 = make_float4(0.f, 0.f, 0.f, 0.f);

    for (int blk = 0; blk < 25; ++blk) {
        // Stage 1: all 5 index/weight pairs (LDS, warp-uniform broadcast).
        float2 iw[5];
        #pragma unroll
        for (int j = 0; j < 5; ++j)
            iw[j] = s_iw[(blk * 5 + j) * 2 + g];

        // Stage 2: 5 independent LDG.128 back-to-back (MLP = 5).
        uint4 v[5];
        #pragma unroll
        for (int j = 0; j < 5; ++j)
            v[j] = __ldg(&g_peh[__float_as_int(iw[j].x) + t64]);

        // Stage 3: fp16 accumulate (chain length 5), then flush to f32.
        __half2 h0 = __half2half2(__ushort_as_half(0));
        __half2 h1 = h0, h2 = h0, h3 = h0;
        #pragma unroll
        for (int j = 0; j < 5; ++j) {
            const unsigned wb = __float_as_uint(iw[j].y);
            const __half2  w2 = *reinterpret_cast<const __half2*>(&wb);
            h0 = __hfma2(*reinterpret_cast<const __half2*>(&v[j].x), w2, h0);
            h1 = __hfma2(*reinterpret_cast<const __half2*>(&v[j].y), w2, h1);
            h2 = __hfma2(*reinterpret_cast<const __half2*>(&v[j].z), w2, h2);
            h3 = __hfma2(*reinterpret_cast<const __half2*>(&v[j].w), w2, h3);
        }

        const float2 f0 = __half22float2(h0);
        const float2 f1 = __half22float2(h1);
        const float2 f2 = __half22float2(h2);
        const float2 f3 = __half22float2(h3);
        a0.x += f0.x; a0.y += f0.y; a0.z += f1.x; a0.w += f1.y;
        a1.x += f2.x; a1.y += f2.y; a1.z += f3.x; a1.w += f3.y;
    }

    // Combine the two peak-groups, then atomically add into out
    // (exactly 2 contenders per address: the two peak-half CTAs).
    if (g == 1) {
        s_red[t64]      = a0;
        s_red[64 + t64] = a1;
    }
    __syncthreads();
    if (g == 0) {
        const float4 b0 = s_red[t64];
        const float4 b1 = s_red[64 + t64];
        a0.x += b0.x; a0.y += b0.y; a0.z += b0.z; a0.w += b0.w;
        a1.x += b1.x; a1.y += b1.y; a1.z += b1.z; a1.w += b1.w;
        float* orow = out + (long long)b * D_MODEL + 8 * t64;
        atomicAdd(orow + 0, a0.x);
        atomicAdd(orow + 1, a0.y);
        atomicAdd(orow + 2, a0.z);
        atomicAdd(orow + 3, a0.w);
        atomicAdd(orow + 4, a1.x);
        atomicAdd(orow + 5, a1.y);
        atomicAdd(orow + 6, a1.z);
        atomicAdd(orow + 7, a1.w);
    }
}

extern "C" void kernel_launch(void* const* d_in, const int* in_sizes, int n_in,
                              void* d_out, int out_size)
{
    const float*  loc   = (const float*)d_in[0];   // [B, 500]
    const float*  inten = (const float*)d_in[1];   // [B, 500]
    const float4* pe4   = (const float4*)d_in[2];  // [30001, 512] f32
    float*        out   = (float*)d_out;           // [B, 512] f32

    const int B = in_sizes[0] / N_PEAKS;           // 1024

    convert_pe_kernel<<<2048, 256>>>(pe4, out);    // 524288 threads == out elems
    SpectrumEncoding_kernel<<<B * 2, 128>>>(loc, inten, out);
}

// round 16
// speedup vs baseline: 1.4167x; 1.0345x over previous
#include <cuda_runtime.h>
#include <cuda_fp16.h>

// SpectrumEncoding: out[b,d] = sum_n pe[ceil(loc[b,n]*10), d] * inten[b,n]
// B=1024, N=500, D=512.
//
// R12-R15 established: fp16 gather wall ~39us (L2 ~58%) is invariant to MLP,
// occupancy, schedule, load width, layout, cache policy. Accepted.
// R16 strips auxiliary cycles: one CTA per batch row (grid 1024, 256 thr =
// 4 groups x 64, mod-4 peak stride, staged-5 loads) -> exclusive output:
// no atomics, no out zeroing. Same 64-reg operating point as R15.

#define N_PEAKS    500
#define D_MODEL    512
#define RESO       10.0f
#define TABLE_ROWS 30001
#define ROW_U4     (D_MODEL / 8) // 64 uint4 (8 halves) per fp16 row

// fp16 copy of pe, rebuilt each call (30.7 MB).
__device__ uint4 g_peh[TABLE_ROWS * ROW_U4];

// ---------------------------------------------------------------------------
// Pass 1: f32 -> f16 convert (8-deep unroll, MLP=8).
// ---------------------------------------------------------------------------
__global__ void convert_pe_kernel(const float4* __restrict__ pe4)
{
    uint2* __restrict__ dst = reinterpret_cast<uint2*>(g_peh);
    const int total  = TABLE_ROWS * (D_MODEL / 4);   // 3,840,128 uint2
    const int stride = gridDim.x * blockDim.x;       // 524,288
    const int i0     = blockIdx.x * blockDim.x + threadIdx.x;

    #pragma unroll 8
    for (int j = 0; j < 8; ++j) {
        const int k = i0 + j * stride;
        if (k < total) {
            float4 v = pe4[k];
            __half2 h0 = __floats2half2_rn(v.x, v.y);
            __half2 h1 = __floats2half2_rn(v.z, v.w);
            uint2 p;
            p.x = *reinterpret_cast<unsigned*>(&h0);
            p.y = *reinterpret_cast<unsigned*>(&h1);
            dst[k] = p;
        }
    }
}

// ---------------------------------------------------------------------------
// Pass 2: gather + weighted reduce. One CTA per batch row, 256 threads =
// 4 groups of 64. Group q handles peaks n = 4*it + q (125 each) in 25
// staged-5 blocks: 5 LDS, 5 independent LDG.128 (MLP=5), fp16 HFMA2 chains
// of 5 flushed to f32. Epilogue: groups 1-3 -> smem, group 0 combines and
// stores directly (exclusive output, no atomics).
// ---------------------------------------------------------------------------
__global__ __launch_bounds__(256, 4)
void SpectrumEncoding_kernel(const float*  __restrict__ loc,
                             const float*  __restrict__ inten,
                             float4*       __restrict__ out4)
{
    __shared__ float2 s_iw[N_PEAKS];     // .x = (idx*ROW_U4) bits, .y = half2(w,w) bits
    __shared__ float4 s_red[3][128];     // partials from groups 1..3 (6 KB)

    const int b   = blockIdx.x;
    const int t   = threadIdx.x;
    const int q   = t >> 6;              // group 0..3 (2 warps each)
    const int t64 = t & 63;

    const float* lrow = loc   + (long long)b * N_PEAKS;
    const float* irow = inten + (long long)b * N_PEAKS;

    for (int n = t; n < N_PEAKS; n += 256) {
        int idx = (int)ceilf(lrow[n] * RESO);
        __half2 w2 = __half2half2(__float2half(irow[n]));
        s_iw[n] = make_float2(__int_as_float(idx * ROW_U4),
                              __uint_as_float(*reinterpret_cast<unsigned*>(&w2)));
    }
    __syncthreads();

    float4 a0 = make_float4(0.f, 0.f, 0.f, 0.f);
    float4 a1 = make_float4(0.f, 0.f, 0.f, 0.f);

    for (int blk = 0; blk < 25; ++blk) {
        // Stage 1: 5 index/weight pairs (LDS, warp-uniform broadcast).
        float2 iw[5];
        #pragma unroll
        for (int j = 0; j < 5; ++j)
            iw[j] = s_iw[(blk * 5 + j) * 4 + q];

        // Stage 2: 5 independent LDG.128 back-to-back (MLP = 5).
        uint4 v[5];
        #pragma unroll
        for (int j = 0; j < 5; ++j)
            v[j] = __ldg(&g_peh[__float_as_int(iw[j].x) + t64]);

        // Stage 3: fp16 accumulate (chain length 5), then flush to f32.
        __half2 h0 = __half2half2(__ushort_as_half(0));
        __half2 h1 = h0, h2 = h0, h3 = h0;
        #pragma unroll
        for (int j = 0; j < 5; ++j) {
            const unsigned wb = __float_as_uint(iw[j].y);
            const __half2  w2 = *reinterpret_cast<const __half2*>(&wb);
            h0 = __hfma2(*reinterpret_cast<const __half2*>(&v[j].x), w2, h0);
            h1 = __hfma2(*reinterpret_cast<const __half2*>(&v[j].y), w2, h1);
            h2 = __hfma2(*reinterpret_cast<const __half2*>(&v[j].z), w2, h2);
            h3 = __hfma2(*reinterpret_cast<const __half2*>(&v[j].w), w2, h3);
        }

        const float2 f0 = __half22float2(h0);
        const float2 f1 = __half22float2(h1);
        const float2 f2 = __half22float2(h2);
        const float2 f3 = __half22float2(h3);
        a0.x += f0.x; a0.y += f0.y; a0.z += f1.x; a0.w += f1.y;
        a1.x += f2.x; a1.y += f2.y; a1.z += f3.x; a1.w += f3.y;
    }

    // Groups 1..3 publish partials; group 0 combines and stores.
    if (q != 0) {
        s_red[q - 1][t64]      = a0;
        s_red[q - 1][64 + t64] = a1;
    }
    __syncthreads();
    if (q == 0) {
        #pragma unroll
        for (int r = 0; r < 3; ++r) {
            const float4 b0 = s_red[r][t64];
            const float4 b1 = s_red[r][64 + t64];
            a0.x += b0.x; a0.y += b0.y; a0.z += b0.z; a0.w += b0.w;
            a1.x += b1.x; a1.y += b1.y; a1.z += b1.z; a1.w += b1.w;
        }
        float4* orow = out4 + (long long)b * (D_MODEL / 4);
        orow[2 * t64]     = a0;
        orow[2 * t64 + 1] = a1;
    }
}

extern "C" void kernel_launch(void* const* d_in, const int* in_sizes, int n_in,
                              void* d_out, int out_size)
{
    const float*  loc   = (const float*)d_in[0];   // [B, 500]
    const float*  inten = (const float*)d_in[1];   // [B, 500]
    const float4* pe4   = (const float4*)d_in[2];  // [30001, 512] f32
    float4*       out4  = (float4*)d_out;          // [B, 512] f32

    const int B = in_sizes[0] / N_PEAKS;           // 1024

    convert_pe_kernel<<<2048, 256>>>(pe4);
    SpectrumEncoding_kernel<<<B, 256>>>(loc, inten, out4);
}

// round 17
// speedup vs baseline: 1.4763x; 1.0421x over previous
#include <cuda_runtime.h>
#include <cuda_fp16.h>

// SpectrumEncoding: out[b,d] = sum_n pe[ceil(loc[b,n]*10), d] * inten[b,n]
// B=1024, N=500, D=512.
//
// Gather wall (~37us, L2 ~62%) proven invariant to MLP/occ/schedule/width/
// layout/cache-policy (R12-R16). R17 targets launch geometry instead:
// grid 512 x 2 rows/CTA = ONE fully-resident wave (was 1.73 ragged waves on
// a non-saturated kernel -> tail latency exposed). Convert: STG.128 stores
// + grid 4096.

#define N_PEAKS    500
#define D_MODEL    512
#define RESO       10.0f
#define TABLE_ROWS 30001
#define ROW_U4     (D_MODEL / 8) // 64 uint4 (8 halves) per fp16 row

// fp16 copy of pe, rebuilt each call (30.7 MB).
__device__ uint4 g_peh[TABLE_ROWS * ROW_U4];

// ---------------------------------------------------------------------------
// Pass 1: f32 -> f16 convert. 2x LDG.128 -> 1x STG.128 per 32B, 4-deep
// independent window per thread.
// ---------------------------------------------------------------------------
__global__ void convert_pe_kernel(const float4* __restrict__ pe4)
{
    uint4* __restrict__ dst = reinterpret_cast<uint4*>(g_peh);
    const int total  = TABLE_ROWS * (D_MODEL / 8);   // 1,920,064 uint4 outputs
    const int stride = gridDim.x * blockDim.x;       // 1,048,576
    const int i0     = blockIdx.x * blockDim.x + threadIdx.x;

    #pragma unroll 4
    for (int j = 0; j < 4; ++j) {
        const int k = i0 + j * stride;
        if (k < total) {
            float4 a = pe4[2 * k];
            float4 b = pe4[2 * k + 1];
            __half2 h0 = __floats2half2_rn(a.x, a.y);
            __half2 h1 = __floats2half2_rn(a.z, a.w);
            __half2 h2 = __floats2half2_rn(b.x, b.y);
            __half2 h3 = __floats2half2_rn(b.z, b.w);
            uint4 p;
            p.x = *reinterpret_cast<unsigned*>(&h0);
            p.y = *reinterpret_cast<unsigned*>(&h1);
            p.z = *reinterpret_cast<unsigned*>(&h2);
            p.w = *reinterpret_cast<unsigned*>(&h3);
            dst[k] = p;
        }
    }
}

// ---------------------------------------------------------------------------
// Pass 2: gather + weighted reduce. Grid 512 = ONE resident wave at
// 4 CTAs/SM; each CTA processes 2 batch rows sequentially. 256 threads =
// 4 groups of 64; group q takes peaks n = 4*it + q in 25 staged-5 blocks
// (5 LDS, 5 independent LDG.128, HFMA2 chains of 5 -> f32). Epilogue per
// row: groups 1-3 -> smem, group 0 combines + STG.128 (exclusive output).
// ---------------------------------------------------------------------------
__global__ __launch_bounds__(256, 4)
void SpectrumEncoding_kernel(const float*  __restrict__ loc,
                             const float*  __restrict__ inten,
                             float4*       __restrict__ out4)
{
    __shared__ float2 s_iw[N_PEAKS];     // .x = (idx*ROW_U4) bits, .y = half2(w,w) bits
    __shared__ float4 s_red[3][128];     // partials from groups 1..3 (6 KB)

    const int t   = threadIdx.x;
    const int q   = t >> 6;              // group 0..3 (2 warps each)
    const int t64 = t & 63;

    for (int rr = 0; rr < 2; ++rr) {
        const int b = blockIdx.x * 2 + rr;

        const float* lrow = loc   + (long long)b * N_PEAKS;
        const float* irow = inten + (long long)b * N_PEAKS;

        if (rr) __syncthreads();         // s_iw reuse barrier
        for (int n = t; n < N_PEAKS; n += 256) {
            int idx = (int)ceilf(lrow[n] * RESO);
            __half2 w2 = __half2half2(__float2half(irow[n]));
            s_iw[n] = make_float2(__int_as_float(idx * ROW_U4),
                                  __uint_as_float(*reinterpret_cast<unsigned*>(&w2)));
        }
        __syncthreads();

        float4 a0 = make_float4(0.f, 0.f, 0.f, 0.f);
        float4 a1 = make_float4(0.f, 0.f, 0.f, 0.f);

        for (int blk = 0; blk < 25; ++blk) {
            // Stage 1: 5 index/weight pairs (LDS, warp-uniform broadcast).
            float2 iw[5];
            #pragma unroll
            for (int j = 0; j < 5; ++j)
                iw[j] = s_iw[(blk * 5 + j) * 4 + q];

            // Stage 2: 5 independent LDG.128 back-to-back (MLP = 5).
            uint4 v[5];
            #pragma unroll
            for (int j = 0; j < 5; ++j)
                v[j] = __ldg(&g_peh[__float_as_int(iw[j].x) + t64]);

            // Stage 3: fp16 accumulate (chain length 5), then flush to f32.
            __half2 h0 = __half2half2(__ushort_as_half(0));
            __half2 h1 = h0, h2 = h0, h3 = h0;
            #pragma unroll
            for (int j = 0; j < 5; ++j) {
                const unsigned wb = __float_as_uint(iw[j].y);
                const __half2  w2 = *reinterpret_cast<const __half2*>(&wb);
                h0 = __hfma2(*reinterpret_cast<const __half2*>(&v[j].x), w2, h0);
                h1 = __hfma2(*reinterpret_cast<const __half2*>(&v[j].y), w2, h1);
                h2 = __hfma2(*reinterpret_cast<const __half2*>(&v[j].z), w2, h2);
                h3 = __hfma2(*reinterpret_cast<const __half2*>(&v[j].w), w2, h3);
            }

            const float2 f0 = __half22float2(h0);
            const float2 f1 = __half22float2(h1);
            const float2 f2 = __half22float2(h2);
            const float2 f3 = __half22float2(h3);
            a0.x += f0.x; a0.y += f0.y; a0.z += f1.x; a0.w += f1.y;
            a1.x += f2.x; a1.y += f2.y; a1.z += f3.x; a1.w += f3.y;
        }

        // Groups 1..3 publish partials; group 0 combines and stores.
        if (q != 0) {
            s_red[q - 1][t64]      = a0;
            s_red[q - 1][64 + t64] = a1;
        }
        __syncthreads();
        if (q == 0) {
            #pragma unroll
            for (int r = 0; r < 3; ++r) {
                const float4 b0 = s_red[r][t64];
                const float4 b1 = s_red[r][64 + t64];
                a0.x += b0.x; a0.y += b0.y; a0.z += b0.z; a0.w += b0.w;
                a1.x += b1.x; a1.y += b1.y; a1.z += b1.z; a1.w += b1.w;
            }
            float4* orow = out4 + (long long)b * (D_MODEL / 4);
            orow[2 * t64]     = a0;
            orow[2 * t64 + 1] = a1;
        }
    }
}

extern "C" void kernel_launch(void* const* d_in, const int* in_sizes, int n_in,
                              void* d_out, int out_size)
{
    const float*  loc   = (const float*)d_in[0];   // [B, 500]
    const float*  inten = (const float*)d_in[1];   // [B, 500]
    const float4* pe4   = (const float4*)d_in[2];  // [30001, 512] f32
    float4*       out4  = (float4*)d_out;          // [B, 512] f32

    const int B = in_sizes[0] / N_PEAKS;           // 1024

    convert_pe_kernel<<<4096, 256>>>(pe4);
    SpectrumEncoding_kernel<<<B / 2, 256>>>(loc, inten, out4);
}